// round 3
// baseline (speedup 1.0000x reference)
#include <cuda_runtime.h>
#include <cstdint>

#define BB 32
#define SS 256
#define TT 128
#define HH 512
#define EENC 512
#define EEMB 256
#define VV 32000
#define KLOG 1024

__device__ float g_kp[BB * SS * HH];
__device__ float g_embT[TT * EEMB * BB];
__device__ float g_st[2][4][HH * BB];   // 0=h0 1=c0 2=h1 3=c1, [unit][batch]
__device__ float g_qp[BB * HH];
__device__ float g_ctxT[EENC * BB];
__device__ float g_A[BB * TT * KLOG];

__device__ __forceinline__ float ex2f(float x){ float y; asm("ex2.approx.f32 %0,%1;":"=f"(y):"f"(x)); return y; }
__device__ __forceinline__ float rcpf(float x){ float y; asm("rcp.approx.f32 %0,%1;":"=f"(y):"f"(x)); return y; }
__device__ __forceinline__ float tanh_fast(float x){ float y; asm("tanh.approx.f32 %0,%1;":"=f"(y):"f"(x)); return y; }
__device__ __forceinline__ float sigm(float x){ return rcpf(1.f + ex2f(-1.44269504f * x)); }
__device__ __forceinline__ float tanh_acc(float x){ float e = ex2f(2.88539008f * x); return 1.f - 2.f * rcpf(e + 1.f); }

__global__ void init_kernel()
{
    int i = blockIdx.x * blockDim.x + threadIdx.x;
    if (i < 4 * HH * BB) g_st[0][0][i] = 0.f;
}

__global__ void embed_kernel(const int* __restrict__ tok, const float* __restrict__ emb)
{
    int idx = blockIdx.x * blockDim.x + threadIdx.x;
    if (idx >= TT * EEMB * BB) return;
    int b = idx & 31, k = (idx >> 5) & (EEMB - 1), t = idx >> 13;
    g_embT[idx] = emb[(size_t)tok[b * TT + t] * EEMB + k];
}

// C[M,N] = A[M,K] @ Bw[N,K]^T + bias[N], tf32 mma, M%128==0, N%128==0, K%32==0
__global__ void __launch_bounds__(256) gemm_tf32(
    const float* __restrict__ A, const float* __restrict__ Bw,
    const float* __restrict__ bias, float* __restrict__ C,
    int M, int N, int K)
{
    __shared__ float As[128 * 36];
    __shared__ float Bs[128 * 36];
    const int tid = threadIdx.x, lane = tid & 31, warp = tid >> 5;
    const int g = lane >> 2, c = lane & 3;
    const int wm = (warp >> 1) * 32, wn = (warp & 1) * 64;
    const int bm = blockIdx.y * 128, bn = blockIdx.x * 128;
    const int kg = tid & 7, rb = tid >> 3;
    const float* Aptr = A + (size_t)(bm + rb) * K + kg * 4;
    const float* Bptr = Bw + (size_t)(bn + rb) * K + kg * 4;

    float acc[2][8][4];
#pragma unroll
    for (int mi = 0; mi < 2; mi++)
#pragma unroll
        for (int ni = 0; ni < 8; ni++) { acc[mi][ni][0]=0;acc[mi][ni][1]=0;acc[mi][ni][2]=0;acc[mi][ni][3]=0; }

    for (int kt = 0; kt < K; kt += 32) {
        float4 av[4], bv[4];
#pragma unroll
        for (int p = 0; p < 4; p++) {
            av[p] = *(const float4*)(Aptr + (size_t)(p * 32) * K + kt);
            bv[p] = *(const float4*)(Bptr + (size_t)(p * 32) * K + kt);
        }
        __syncthreads();
#pragma unroll
        for (int p = 0; p < 4; p++) {
            *(float4*)&As[(rb + p * 32) * 36 + kg * 4] = av[p];
            *(float4*)&Bs[(rb + p * 32) * 36 + kg * 4] = bv[p];
        }
        __syncthreads();
#pragma unroll
        for (int ks = 0; ks < 4; ks++) {
            const int k0 = ks * 8;
            unsigned a[2][4], bf[8][2];
#pragma unroll
            for (int mi = 0; mi < 2; mi++) {
                int r0 = (wm + mi * 16 + g) * 36 + k0 + c;
                a[mi][0] = __float_as_uint(As[r0]);
                a[mi][1] = __float_as_uint(As[r0 + 8 * 36]);
                a[mi][2] = __float_as_uint(As[r0 + 4]);
                a[mi][3] = __float_as_uint(As[r0 + 8 * 36 + 4]);
            }
#pragma unroll
            for (int ni = 0; ni < 8; ni++) {
                int r0 = (wn + ni * 8 + g) * 36 + k0 + c;
                bf[ni][0] = __float_as_uint(Bs[r0]);
                bf[ni][1] = __float_as_uint(Bs[r0 + 4]);
            }
#pragma unroll
            for (int mi = 0; mi < 2; mi++)
#pragma unroll
                for (int ni = 0; ni < 8; ni++)
                    asm volatile(
                        "mma.sync.aligned.m16n8k8.row.col.f32.tf32.tf32.f32 "
                        "{%0,%1,%2,%3},{%4,%5,%6,%7},{%8,%9},{%0,%1,%2,%3};"
                        : "+f"(acc[mi][ni][0]), "+f"(acc[mi][ni][1]),
                          "+f"(acc[mi][ni][2]), "+f"(acc[mi][ni][3])
                        : "r"(a[mi][0]), "r"(a[mi][1]), "r"(a[mi][2]), "r"(a[mi][3]),
                          "r"(bf[ni][0]), "r"(bf[ni][1]));
        }
    }
#pragma unroll
    for (int mi = 0; mi < 2; mi++) {
        const int r = bm + wm + mi * 16 + g;
#pragma unroll
        for (int ni = 0; ni < 8; ni++) {
            const int col = bn + wn + ni * 8 + 2 * c;
            const float b0 = bias[col], b1 = bias[col + 1];
            *(float2*)&C[(size_t)r * N + col]       = make_float2(acc[mi][ni][0] + b0, acc[mi][ni][1] + b1);
            *(float2*)&C[(size_t)(r + 8) * N + col] = make_float2(acc[mi][ni][2] + b0, acc[mi][ni][3] + b1);
        }
    }
}

__global__ void __launch_bounds__(256) qproj_kernel(
    int rbuf, const float* __restrict__ Wq, const float* __restrict__ bq)
{
    int tid = blockIdx.x * 256 + threadIdx.x;
    int h = tid >> 5, b = tid & 31;
    const float* h1 = g_st[rbuf][2];
    const float* w = Wq + (size_t)h * HH;
    float acc = 0.f;
    for (int k = 0; k < HH; k += 4) {
        float4 wv = *(const float4*)(w + k);
        acc += wv.x * h1[k * 32 + b] + wv.y * h1[(k + 1) * 32 + b]
             + wv.z * h1[(k + 2) * 32 + b] + wv.w * h1[(k + 3) * 32 + b];
    }
    g_qp[b * HH + h] = acc + bq[h];
}

__global__ void __launch_bounds__(256) attn_kernel(
    const float* __restrict__ enc, const float* __restrict__ vvec, int t)
{
    const int b = blockIdx.x;
    const int tid = threadIdx.x, lane = tid & 31, warp = tid >> 5;
    __shared__ float sc[SS];
    __shared__ float red[8];

    float qv[16], vv[16];
#pragma unroll
    for (int i = 0; i < 16; i++) {
        qv[i] = g_qp[b * HH + i * 32 + lane];
        vv[i] = vvec[i * 32 + lane];
    }
    for (int s = warp; s < SS; s += 8) {
        const float* kp = g_kp + ((size_t)b * SS + s) * HH;
        float acc = 0.f;
#pragma unroll
        for (int i = 0; i < 16; i++)
            acc += vv[i] * tanh_fast(kp[i * 32 + lane] + qv[i]);
#pragma unroll
        for (int o = 16; o; o >>= 1) acc += __shfl_xor_sync(0xffffffffu, acc, o);
        if (lane == 0) sc[s] = acc;
    }
    __syncthreads();

    float x = sc[tid];
    float m = x;
#pragma unroll
    for (int o = 16; o; o >>= 1) m = fmaxf(m, __shfl_xor_sync(0xffffffffu, m, o));
    if (lane == 0) red[warp] = m;
    __syncthreads();
    float bmax = red[0];
#pragma unroll
    for (int w = 1; w < 8; w++) bmax = fmaxf(bmax, red[w]);
    float e = ex2f(1.44269504f * (x - bmax));
    float se = e;
#pragma unroll
    for (int o = 16; o; o >>= 1) se += __shfl_xor_sync(0xffffffffu, se, o);
    __syncthreads();
    if (lane == 0) red[warp] = se;
    __syncthreads();
    float tot = 0.f;
#pragma unroll
    for (int w = 0; w < 8; w++) tot += red[w];
    float wgt = e * rcpf(tot);
    sc[tid] = wgt;
    __syncthreads();

    const float* eb = enc + (size_t)b * SS * EENC;
    float a0 = 0.f, a1 = 0.f;
    for (int s = 0; s < SS; s++) {
        float ws = sc[s];
        a0 += ws * eb[s * EENC + tid];
        a1 += ws * eb[s * EENC + tid + 256];
    }
    g_ctxT[tid * 32 + b] = a0;
    g_ctxT[(tid + 256) * 32 + b] = a1;
    float* arow = g_A + ((size_t)b * TT + t) * KLOG + HH;
    arow[tid] = a0;
    arow[tid + 256] = a1;
}

__global__ void __launch_bounds__(256) lstm_kernel(
    int layer, int t, int rbuf,
    const float* __restrict__ Wih, const float* __restrict__ Whh,
    const float* __restrict__ bih, const float* __restrict__ bhh)
{
    int tid = blockIdx.x * 256 + threadIdx.x;
    int j = tid >> 5, b = tid & 31;
    int wbuf = rbuf ^ 1;

    const float *xA, *xB, *hin, *cin;
    float *hout, *cout;
    int lenA, lenB;
    if (layer == 0) {
        xA = g_embT + (size_t)t * EEMB * BB; lenA = EEMB;
        xB = g_ctxT;                          lenB = EENC;
        hin = g_st[rbuf][0]; cin = g_st[rbuf][1];
        hout = g_st[wbuf][0]; cout = g_st[wbuf][1];
    } else {
        xA = g_st[wbuf][0]; lenA = HH;
        xB = nullptr;        lenB = 0;
        hin = g_st[rbuf][2]; cin = g_st[rbuf][3];
        hout = g_st[wbuf][2]; cout = g_st[wbuf][3];
    }
    const int K1 = lenA + lenB;
    const float* w0 = Wih + (size_t)j * K1;
    const float* w1 = Wih + (size_t)(HH + j) * K1;
    const float* w2 = Wih + (size_t)(2 * HH + j) * K1;
    const float* w3 = Wih + (size_t)(3 * HH + j) * K1;

    float ai = 0.f, af = 0.f, ag = 0.f, ao = 0.f;
    for (int k = 0; k < lenA; k += 4) {
        float x0 = xA[k * 32 + b], x1 = xA[(k + 1) * 32 + b];
        float x2 = xA[(k + 2) * 32 + b], x3 = xA[(k + 3) * 32 + b];
        float4 wv;
        wv = *(const float4*)(w0 + k); ai += wv.x*x0 + wv.y*x1 + wv.z*x2 + wv.w*x3;
        wv = *(const float4*)(w1 + k); af += wv.x*x0 + wv.y*x1 + wv.z*x2 + wv.w*x3;
        wv = *(const float4*)(w2 + k); ag += wv.x*x0 + wv.y*x1 + wv.z*x2 + wv.w*x3;
        wv = *(const float4*)(w3 + k); ao += wv.x*x0 + wv.y*x1 + wv.z*x2 + wv.w*x3;
    }
    if (lenB) {
        for (int k = 0; k < lenB; k += 4) {
            float x0 = xB[k * 32 + b], x1 = xB[(k + 1) * 32 + b];
            float x2 = xB[(k + 2) * 32 + b], x3 = xB[(k + 3) * 32 + b];
            float4 wv;
            wv = *(const float4*)(w0 + lenA + k); ai += wv.x*x0 + wv.y*x1 + wv.z*x2 + wv.w*x3;
            wv = *(const float4*)(w1 + lenA + k); af += wv.x*x0 + wv.y*x1 + wv.z*x2 + wv.w*x3;
            wv = *(const float4*)(w2 + lenA + k); ag += wv.x*x0 + wv.y*x1 + wv.z*x2 + wv.w*x3;
            wv = *(const float4*)(w3 + lenA + k); ao += wv.x*x0 + wv.y*x1 + wv.z*x2 + wv.w*x3;
        }
    }
    const float* u0 = Whh + (size_t)j * HH;
    const float* u1 = Whh + (size_t)(HH + j) * HH;
    const float* u2 = Whh + (size_t)(2 * HH + j) * HH;
    const float* u3 = Whh + (size_t)(3 * HH + j) * HH;
    for (int k = 0; k < HH; k += 4) {
        float x0 = hin[k * 32 + b], x1 = hin[(k + 1) * 32 + b];
        float x2 = hin[(k + 2) * 32 + b], x3 = hin[(k + 3) * 32 + b];
        float4 wv;
        wv = *(const float4*)(u0 + k); ai += wv.x*x0 + wv.y*x1 + wv.z*x2 + wv.w*x3;
        wv = *(const float4*)(u1 + k); af += wv.x*x0 + wv.y*x1 + wv.z*x2 + wv.w*x3;
        wv = *(const float4*)(u2 + k); ag += wv.x*x0 + wv.y*x1 + wv.z*x2 + wv.w*x3;
        wv = *(const float4*)(u3 + k); ao += wv.x*x0 + wv.y*x1 + wv.z*x2 + wv.w*x3;
    }

    float iv = sigm(ai + bih[j] + bhh[j]);
    float fv = sigm(af + bih[HH + j] + bhh[HH + j]);
    float gv = tanh_acc(ag + bih[2 * HH + j] + bhh[2 * HH + j]);
    float ov = sigm(ao + bih[3 * HH + j] + bhh[3 * HH + j]);

    float cn = fv * cin[j * 32 + b] + iv * gv;
    float hn = ov * tanh_acc(cn);
    cout[j * 32 + b] = cn;
    hout[j * 32 + b] = hn;
    if (layer == 1)
        g_A[((size_t)b * TT + t) * KLOG + j] = hn;
}

__global__ void epilogue_kernel(float* __restrict__ out)
{
    int idx = blockIdx.x * blockDim.x + threadIdx.x;
    if (idx >= 2 * 2 * BB * HH) return;
    int part = idx >> 15;
    int rem = idx & 32767;
    int l = rem >> 14;
    int bb = (rem >> 9) & 31;
    int k = rem & 511;
    int which = (part == 0) ? (l ? 2 : 0) : (l ? 3 : 1);
    out[(size_t)BB * TT * VV + idx] = g_st[0][which][k * 32 + bb];
}

extern "C" void kernel_launch(void* const* d_in, const int* in_sizes, int n_in,
                              void* d_out, int out_size)
{
    const float* enc  = (const float*)d_in[0];
    const int*   tok  = (const int*)  d_in[1];
    const float* emb  = (const float*)d_in[2];
    const float* Wq   = (const float*)d_in[3];
    const float* bq   = (const float*)d_in[4];
    const float* Wk   = (const float*)d_in[5];
    const float* bk   = (const float*)d_in[6];
    const float* vvec = (const float*)d_in[7];
    const float* Wih0 = (const float*)d_in[8];
    const float* Whh0 = (const float*)d_in[9];
    const float* bih0 = (const float*)d_in[10];
    const float* bhh0 = (const float*)d_in[11];
    const float* Wih1 = (const float*)d_in[12];
    const float* Whh1 = (const float*)d_in[13];
    const float* bih1 = (const float*)d_in[14];
    const float* bhh1 = (const float*)d_in[15];
    const float* Wout = (const float*)d_in[16];
    const float* bout = (const float*)d_in[17];
    float* out = (float*)d_out;

    float* kp;    cudaGetSymbolAddress((void**)&kp,  g_kp);
    float* Amat;  cudaGetSymbolAddress((void**)&Amat, g_A);

    init_kernel<<<(4 * HH * BB + 255) / 256, 256>>>();
    embed_kernel<<<(TT * EEMB * BB + 255) / 256, 256>>>(tok, emb);

    // key_proj = enc @ Wk^T + bk : M = B*S = 8192, N = 512, K = 512
    {
        dim3 grid(HH / 128, (BB * SS) / 128);
        gemm_tf32<<<grid, 256>>>(enc, Wk, bk, kp, BB * SS, HH, EENC);
    }

    for (int t = 0; t < TT; t++) {
        int rbuf = t & 1;
        qproj_kernel<<<(HH * BB) / 256, 256>>>(rbuf, Wq, bq);
        attn_kernel<<<BB, 256>>>(enc, vvec, t);
        lstm_kernel<<<(HH * BB) / 256, 256>>>(0, t, rbuf, Wih0, Whh0, bih0, bhh0);
        lstm_kernel<<<(HH * BB) / 256, 256>>>(1, t, rbuf, Wih1, Whh1, bih1, bhh1);
    }

    // logits: M = B*T = 4096, N = V = 32000, K = 1024
    {
        dim3 grid(VV / 128, (BB * TT) / 128);
        gemm_tf32<<<grid, 256>>>(Amat, Wout, bout, out, BB * TT, VV, KLOG);
    }

    epilogue_kernel<<<(2 * 2 * BB * HH + 255) / 256, 256>>>(out);
}

// round 4
// speedup vs baseline: 2.2518x; 2.2518x over previous
#include <cuda_runtime.h>
#include <cstdint>

#define BB 32
#define SS 256
#define TT 128
#define HH 512
#define EENC 512
#define EEMB 256
#define VV 32000
#define KLOG 1024
#define NB 128

__device__ float g_kp[BB * SS * HH];
__device__ float g_embT[TT * EEMB * BB];
__device__ float g_st[2][4][HH * BB];   // 0=h0 1=c0 2=h1 3=c1, [unit][batch]
__device__ float g_qp[BB * HH];
__device__ float g_ctxT[EENC * BB];
__device__ float g_sc[BB * SS];
__device__ float g_A[BB * TT * KLOG];
__device__ unsigned g_cnt;

__device__ __forceinline__ float ex2f(float x){ float y; asm("ex2.approx.f32 %0,%1;":"=f"(y):"f"(x)); return y; }
__device__ __forceinline__ float rcpf(float x){ float y; asm("rcp.approx.f32 %0,%1;":"=f"(y):"f"(x)); return y; }
__device__ __forceinline__ float tanh_fast(float x){ float y; asm("tanh.approx.f32 %0,%1;":"=f"(y):"f"(x)); return y; }
__device__ __forceinline__ float sigm(float x){ return rcpf(1.f + ex2f(-1.44269504f * x)); }
__device__ __forceinline__ float tanh_acc(float x){ float e = ex2f(2.88539008f * x); return 1.f - 2.f * rcpf(e + 1.f); }

__global__ void init_kernel()
{
    int i = blockIdx.x * blockDim.x + threadIdx.x;
    if (i < 4 * HH * BB) g_st[0][0][i] = 0.f;
    if (i == 0) g_cnt = 0u;
}

__global__ void embed_kernel(const int* __restrict__ tok, const float* __restrict__ emb)
{
    int idx = blockIdx.x * blockDim.x + threadIdx.x;
    if (idx >= TT * EEMB * BB) return;
    int b = idx & 31, k = (idx >> 5) & (EEMB - 1), t = idx >> 13;
    g_embT[idx] = emb[(size_t)tok[b * TT + t] * EEMB + k];
}

// C[M,N] = A[M,K] @ Bw[N,K]^T + bias[N], tf32 mma
__global__ void __launch_bounds__(256) gemm_tf32(
    const float* __restrict__ A, const float* __restrict__ Bw,
    const float* __restrict__ bias, float* __restrict__ C,
    int M, int N, int K)
{
    __shared__ float As[128 * 36];
    __shared__ float Bs[128 * 36];
    const int tid = threadIdx.x, lane = tid & 31, warp = tid >> 5;
    const int g = lane >> 2, c = lane & 3;
    const int wm = (warp >> 1) * 32, wn = (warp & 1) * 64;
    const int bm = blockIdx.y * 128, bn = blockIdx.x * 128;
    const int kg = tid & 7, rb = tid >> 3;
    const float* Aptr = A + (size_t)(bm + rb) * K + kg * 4;
    const float* Bptr = Bw + (size_t)(bn + rb) * K + kg * 4;

    float acc[2][8][4];
#pragma unroll
    for (int mi = 0; mi < 2; mi++)
#pragma unroll
        for (int ni = 0; ni < 8; ni++) { acc[mi][ni][0]=0;acc[mi][ni][1]=0;acc[mi][ni][2]=0;acc[mi][ni][3]=0; }

    for (int kt = 0; kt < K; kt += 32) {
        float4 av[4], bv[4];
#pragma unroll
        for (int p = 0; p < 4; p++) {
            av[p] = *(const float4*)(Aptr + (size_t)(p * 32) * K + kt);
            bv[p] = *(const float4*)(Bptr + (size_t)(p * 32) * K + kt);
        }
        __syncthreads();
#pragma unroll
        for (int p = 0; p < 4; p++) {
            *(float4*)&As[(rb + p * 32) * 36 + kg * 4] = av[p];
            *(float4*)&Bs[(rb + p * 32) * 36 + kg * 4] = bv[p];
        }
        __syncthreads();
#pragma unroll
        for (int ks = 0; ks < 4; ks++) {
            const int k0 = ks * 8;
            unsigned a[2][4], bf[8][2];
#pragma unroll
            for (int mi = 0; mi < 2; mi++) {
                int r0 = (wm + mi * 16 + g) * 36 + k0 + c;
                a[mi][0] = __float_as_uint(As[r0]);
                a[mi][1] = __float_as_uint(As[r0 + 8 * 36]);
                a[mi][2] = __float_as_uint(As[r0 + 4]);
                a[mi][3] = __float_as_uint(As[r0 + 8 * 36 + 4]);
            }
#pragma unroll
            for (int ni = 0; ni < 8; ni++) {
                int r0 = (wn + ni * 8 + g) * 36 + k0 + c;
                bf[ni][0] = __float_as_uint(Bs[r0]);
                bf[ni][1] = __float_as_uint(Bs[r0 + 4]);
            }
#pragma unroll
            for (int mi = 0; mi < 2; mi++)
#pragma unroll
                for (int ni = 0; ni < 8; ni++)
                    asm volatile(
                        "mma.sync.aligned.m16n8k8.row.col.f32.tf32.tf32.f32 "
                        "{%0,%1,%2,%3},{%4,%5,%6,%7},{%8,%9},{%0,%1,%2,%3};"
                        : "+f"(acc[mi][ni][0]), "+f"(acc[mi][ni][1]),
                          "+f"(acc[mi][ni][2]), "+f"(acc[mi][ni][3])
                        : "r"(a[mi][0]), "r"(a[mi][1]), "r"(a[mi][2]), "r"(a[mi][3]),
                          "r"(bf[ni][0]), "r"(bf[ni][1]));
        }
    }
#pragma unroll
    for (int mi = 0; mi < 2; mi++) {
        const int r = bm + wm + mi * 16 + g;
#pragma unroll
        for (int ni = 0; ni < 8; ni++) {
            const int col = bn + wn + ni * 8 + 2 * c;
            const float b0 = bias[col], b1 = bias[col + 1];
            *(float2*)&C[(size_t)r * N + col]       = make_float2(acc[mi][ni][0] + b0, acc[mi][ni][1] + b1);
            *(float2*)&C[(size_t)(r + 8) * N + col] = make_float2(acc[mi][ni][2] + b0, acc[mi][ni][3] + b1);
        }
    }
}

// -------------------- persistent megakernel for the time loop --------------------
__device__ __forceinline__ void grid_bar(unsigned target)
{
    __syncthreads();
    if (threadIdx.x == 0) {
        __threadfence();
        atomicAdd(&g_cnt, 1u);
        while (*((volatile unsigned*)&g_cnt) < target) { }
        __threadfence();
    }
    __syncthreads();
}

template<int LEN>
__device__ __forceinline__ void dotacc(const float* __restrict__ w0, const float* __restrict__ w1,
                                       const float* __restrict__ x, int lane, float& a0, float& a1)
{
#pragma unroll 4
    for (int k = 0; k < LEN; k += 4) {
        float x0 = __ldcg(x + k * 32 + lane);
        float x1 = __ldcg(x + (k + 1) * 32 + lane);
        float x2 = __ldcg(x + (k + 2) * 32 + lane);
        float x3 = __ldcg(x + (k + 3) * 32 + lane);
        float4 w0v = __ldg((const float4*)(w0 + k));
        float4 w1v = __ldg((const float4*)(w1 + k));
        a0 += w0v.x * x0 + w0v.y * x1 + w0v.z * x2 + w0v.w * x3;
        a1 += w1v.x * x0 + w1v.y * x1 + w1v.z * x2 + w1v.w * x3;
    }
}

template<int LAYER>
__device__ __forceinline__ void lstm_phase(
    int t, int rbuf, int jj, bool odd, int pair, int lane,
    const float* __restrict__ Wih, const float* __restrict__ Whh,
    const float* __restrict__ bih, const float* __restrict__ bhh,
    float (*s_a)[32], float (*s_b)[32])
{
    const int wbuf = rbuf ^ 1;
    const int r0 = (odd ? 2 * HH : 0) + jj;
    const int r1 = (odd ? 3 * HH : HH) + jj;
    float a0 = 0.f, a1 = 0.f;
    if (LAYER == 0) {
        const float* xA = g_embT + (size_t)t * EEMB * BB;
        dotacc<EEMB>(Wih + (size_t)r0 * 768, Wih + (size_t)r1 * 768, xA, lane, a0, a1);
        dotacc<EENC>(Wih + (size_t)r0 * 768 + EEMB, Wih + (size_t)r1 * 768 + EEMB, g_ctxT, lane, a0, a1);
        dotacc<HH>(Whh + (size_t)r0 * HH, Whh + (size_t)r1 * HH, g_st[rbuf][0], lane, a0, a1);
    } else {
        dotacc<HH>(Wih + (size_t)r0 * HH, Wih + (size_t)r1 * HH, g_st[wbuf][0], lane, a0, a1);
        dotacc<HH>(Whh + (size_t)r0 * HH, Whh + (size_t)r1 * HH, g_st[rbuf][2], lane, a0, a1);
    }
    a0 += __ldg(bih + r0) + __ldg(bhh + r0);
    a1 += __ldg(bih + r1) + __ldg(bhh + r1);
    if (odd) { s_a[pair][lane] = a0; s_b[pair][lane] = a1; }
    __syncthreads();
    if (!odd) {
        const float* cin = &g_st[rbuf][LAYER ? 3 : 1][0];
        float iv = sigm(a0), fv = sigm(a1);
        float gv = tanh_acc(s_a[pair][lane]);
        float ov = sigm(s_b[pair][lane]);
        float cn = fv * __ldcg(cin + jj * 32 + lane) + iv * gv;
        float hn = ov * tanh_acc(cn);
        g_st[wbuf][LAYER ? 3 : 1][jj * 32 + lane] = cn;
        g_st[wbuf][LAYER ? 2 : 0][jj * 32 + lane] = hn;
        if (LAYER == 1)
            g_A[((size_t)lane * TT + t) * KLOG + jj] = hn;
    }
}

__global__ void __launch_bounds__(256, 1) megakernel(
    const float* __restrict__ enc, const float* __restrict__ vvec,
    const float* __restrict__ Wq, const float* __restrict__ bq,
    const float* __restrict__ Wih0, const float* __restrict__ Whh0,
    const float* __restrict__ bih0, const float* __restrict__ bhh0,
    const float* __restrict__ Wih1, const float* __restrict__ Whh1,
    const float* __restrict__ bih1, const float* __restrict__ bhh1)
{
    const int blk = blockIdx.x, tid = threadIdx.x;
    const int wid = tid >> 5, lane = tid & 31;
    const int gw = blk * 8 + wid;          // 0..1023
    const int pair = wid >> 1;             // 0..3
    const bool odd = wid & 1;
    const int jj = blk * 4 + pair;         // 0..511

    __shared__ float s_a[4][32], s_b[4][32];
    __shared__ float s_w[SS];
    __shared__ float s_c[2][128];
    __shared__ float s_red[16];

    unsigned bar = 0;

    for (int t = 0; t < TT; t++) {
        const int rbuf = t & 1;

        // ---- P1: q projection (warp pair splits K) ----
        {
            const float* w  = Wq + (size_t)jj * HH + (odd ? 256 : 0);
            const float* h1 = &g_st[rbuf][2][odd ? 256 * 32 : 0];
            float acc = 0.f;
#pragma unroll 4
            for (int k = 0; k < 256; k += 4) {
                float x0 = __ldcg(h1 + k * 32 + lane);
                float x1 = __ldcg(h1 + (k + 1) * 32 + lane);
                float x2 = __ldcg(h1 + (k + 2) * 32 + lane);
                float x3 = __ldcg(h1 + (k + 3) * 32 + lane);
                float4 wv = __ldg((const float4*)(w + k));
                acc += wv.x * x0 + wv.y * x1 + wv.z * x2 + wv.w * x3;
            }
            if (odd) s_a[pair][lane] = acc;
            __syncthreads();
            if (!odd) g_qp[lane * HH + jj] = acc + s_a[pair][lane] + __ldg(bq + jj);
        }
        grid_bar(++bar * NB);

        // ---- P2: attention scores ----
        {
            const int b = gw >> 5, sbase = (gw & 31) * 8;
            float qv[16], vv[16];
#pragma unroll
            for (int i = 0; i < 16; i++) {
                qv[i] = __ldcg(&g_qp[b * HH + i * 32 + lane]);
                vv[i] = __ldg(vvec + i * 32 + lane);
            }
#pragma unroll
            for (int si = 0; si < 8; si++) {
                const float* kp = g_kp + ((size_t)b * SS + sbase + si) * HH;
                float acc = 0.f;
#pragma unroll
                for (int i = 0; i < 16; i++)
                    acc += vv[i] * tanh_fast(__ldg(kp + i * 32 + lane) + qv[i]);
#pragma unroll
                for (int o = 16; o; o >>= 1) acc += __shfl_xor_sync(0xffffffffu, acc, o);
                if (lane == 0) g_sc[b * SS + sbase + si] = acc;
            }
        }
        grid_bar(++bar * NB);

        // ---- P3: softmax + context ----
        {
            const int b = blk >> 2, ebase = (blk & 3) * 128;
            float x = __ldcg(&g_sc[b * SS + tid]);
            float m = x;
#pragma unroll
            for (int o = 16; o; o >>= 1) m = fmaxf(m, __shfl_xor_sync(0xffffffffu, m, o));
            if (lane == 0) s_red[wid] = m;
            __syncthreads();
            float bm = s_red[0];
#pragma unroll
            for (int w2 = 1; w2 < 8; w2++) bm = fmaxf(bm, s_red[w2]);
            float e = ex2f(1.44269504f * (x - bm));
            float se = e;
#pragma unroll
            for (int o = 16; o; o >>= 1) se += __shfl_xor_sync(0xffffffffu, se, o);
            if (lane == 0) s_red[8 + wid] = se;
            __syncthreads();
            float tot = 0.f;
#pragma unroll
            for (int w2 = 0; w2 < 8; w2++) tot += s_red[8 + w2];
            s_w[tid] = e * rcpf(tot);
            __syncthreads();

            const int el = tid & 127, sh = tid >> 7;
            const float* eb = enc + (size_t)b * SS * EENC + ebase + el;
            float acc = 0.f;
#pragma unroll 4
            for (int s = sh; s < SS; s += 2)
                acc += s_w[s] * __ldg(eb + (size_t)s * EENC);
            s_c[sh][el] = acc;
            __syncthreads();
            if (tid < 128) {
                float v = s_c[0][tid] + s_c[1][tid];
                g_ctxT[(ebase + tid) * 32 + b] = v;
                g_A[((size_t)b * TT + t) * KLOG + HH + ebase + tid] = v;
            }
        }
        grid_bar(++bar * NB);

        // ---- P4: LSTM layer 0 ----
        lstm_phase<0>(t, rbuf, jj, odd, pair, lane, Wih0, Whh0, bih0, bhh0, s_a, s_b);
        grid_bar(++bar * NB);

        // ---- P5: LSTM layer 1 ----
        lstm_phase<1>(t, rbuf, jj, odd, pair, lane, Wih1, Whh1, bih1, bhh1, s_a, s_b);
        grid_bar(++bar * NB);
    }
}

__global__ void epilogue_kernel(float* __restrict__ out)
{
    int idx = blockIdx.x * blockDim.x + threadIdx.x;
    if (idx >= 2 * 2 * BB * HH) return;
    int part = idx >> 15;
    int rem = idx & 32767;
    int l = rem >> 14;
    int bb = (rem >> 9) & 31;
    int k = rem & 511;
    int which = (part == 0) ? (l ? 2 : 0) : (l ? 3 : 1);
    out[(size_t)BB * TT * VV + idx] = g_st[0][which][k * 32 + bb];
}

extern "C" void kernel_launch(void* const* d_in, const int* in_sizes, int n_in,
                              void* d_out, int out_size)
{
    const float* enc  = (const float*)d_in[0];
    const int*   tok  = (const int*)  d_in[1];
    const float* emb  = (const float*)d_in[2];
    const float* Wq   = (const float*)d_in[3];
    const float* bq   = (const float*)d_in[4];
    const float* Wk   = (const float*)d_in[5];
    const float* bk   = (const float*)d_in[6];
    const float* vvec = (const float*)d_in[7];
    const float* Wih0 = (const float*)d_in[8];
    const float* Whh0 = (const float*)d_in[9];
    const float* bih0 = (const float*)d_in[10];
    const float* bhh0 = (const float*)d_in[11];
    const float* Wih1 = (const float*)d_in[12];
    const float* Whh1 = (const float*)d_in[13];
    const float* bih1 = (const float*)d_in[14];
    const float* bhh1 = (const float*)d_in[15];
    const float* Wout = (const float*)d_in[16];
    const float* bout = (const float*)d_in[17];
    float* out = (float*)d_out;

    float* kp;    cudaGetSymbolAddress((void**)&kp,  g_kp);
    float* Amat;  cudaGetSymbolAddress((void**)&Amat, g_A);

    init_kernel<<<(4 * HH * BB + 255) / 256, 256>>>();
    embed_kernel<<<(TT * EEMB * BB + 255) / 256, 256>>>(tok, emb);

    // key_proj = enc @ Wk^T + bk : M=8192, N=512, K=512
    {
        dim3 grid(HH / 128, (BB * SS) / 128);
        gemm_tf32<<<grid, 256>>>(enc, Wk, bk, kp, BB * SS, HH, EENC);
    }

    megakernel<<<NB, 256>>>(enc, vvec, Wq, bq,
                            Wih0, Whh0, bih0, bhh0,
                            Wih1, Whh1, bih1, bhh1);

    // logits: M=4096, N=32000, K=1024
    {
        dim3 grid(VV / 128, (BB * TT) / 128);
        gemm_tf32<<<grid, 256>>>(Amat, Wout, bout, out, BB * TT, VV, KLOG);
    }

    epilogue_kernel<<<(2 * 2 * BB * HH + 255) / 256, 256>>>(out);
}

// round 5
// speedup vs baseline: 2.6830x; 1.1915x over previous
#include <cuda_runtime.h>
#include <cstdint>

#define BB 32
#define SS 256
#define TT 128
#define HH 512
#define EENC 512
#define EEMB 256
#define VV 32000
#define KLOG 1024
#define NB 128

__device__ float g_kp[BB * SS * HH];        // [b*S+s][h]
__device__ float g_emb2[TT * BB * EEMB];    // [(t*B+b)][k]
__device__ float g_h0[2][BB * HH];          // [b][j]
__device__ float g_h1[2][BB * HH];          // [b][j]
__device__ float g_c0[HH * BB];             // [j][b] (thread-private across steps)
__device__ float g_c1[HH * BB];
__device__ float g_qp[BB * HH];             // [b][h]
__device__ float g_ctx[BB * EENC];          // [b][e]
__device__ float g_sc[BB * SS];
__device__ float g_A[BB * TT * KLOG];
__device__ unsigned g_cnt;

__device__ __forceinline__ float ex2f(float x){ float y; asm("ex2.approx.f32 %0,%1;":"=f"(y):"f"(x)); return y; }
__device__ __forceinline__ float rcpf(float x){ float y; asm("rcp.approx.f32 %0,%1;":"=f"(y):"f"(x)); return y; }
__device__ __forceinline__ float tanh_fast(float x){ float y; asm("tanh.approx.f32 %0,%1;":"=f"(y):"f"(x)); return y; }
__device__ __forceinline__ float sigm(float x){ return rcpf(1.f + ex2f(-1.44269504f * x)); }
__device__ __forceinline__ float tanh_acc(float x){ float e = ex2f(2.88539008f * x); return 1.f - 2.f * rcpf(e + 1.f); }

__global__ void init_kernel()
{
    int i = blockIdx.x * blockDim.x + threadIdx.x;
    if (i < BB * HH) {
        g_h0[0][i] = 0.f; g_h1[0][i] = 0.f;
        g_c0[i] = 0.f;    g_c1[i] = 0.f;
    }
    if (i == 0) g_cnt = 0u;
}

__global__ void embed_kernel(const int* __restrict__ tok, const float* __restrict__ emb)
{
    int idx = blockIdx.x * blockDim.x + threadIdx.x;
    if (idx >= TT * BB * EEMB) return;
    int k = idx & (EEMB - 1), b = (idx >> 8) & 31, t = idx >> 13;
    g_emb2[idx] = emb[(size_t)tok[b * TT + t] * EEMB + k];
}

// C[M,N] = A[M,K] @ Bw[N,K]^T + bias[N], tf32 mma
__global__ void __launch_bounds__(256) gemm_tf32(
    const float* __restrict__ A, const float* __restrict__ Bw,
    const float* __restrict__ bias, float* __restrict__ C,
    int M, int N, int K)
{
    __shared__ float As[128 * 36];
    __shared__ float Bs[128 * 36];
    const int tid = threadIdx.x, lane = tid & 31, warp = tid >> 5;
    const int g = lane >> 2, c = lane & 3;
    const int wm = (warp >> 1) * 32, wn = (warp & 1) * 64;
    const int bm = blockIdx.y * 128, bn = blockIdx.x * 128;
    const int kg = tid & 7, rb = tid >> 3;
    const float* Aptr = A + (size_t)(bm + rb) * K + kg * 4;
    const float* Bptr = Bw + (size_t)(bn + rb) * K + kg * 4;

    float acc[2][8][4];
#pragma unroll
    for (int mi = 0; mi < 2; mi++)
#pragma unroll
        for (int ni = 0; ni < 8; ni++) { acc[mi][ni][0]=0;acc[mi][ni][1]=0;acc[mi][ni][2]=0;acc[mi][ni][3]=0; }

    for (int kt = 0; kt < K; kt += 32) {
        float4 av[4], bv[4];
#pragma unroll
        for (int p = 0; p < 4; p++) {
            av[p] = *(const float4*)(Aptr + (size_t)(p * 32) * K + kt);
            bv[p] = *(const float4*)(Bptr + (size_t)(p * 32) * K + kt);
        }
        __syncthreads();
#pragma unroll
        for (int p = 0; p < 4; p++) {
            *(float4*)&As[(rb + p * 32) * 36 + kg * 4] = av[p];
            *(float4*)&Bs[(rb + p * 32) * 36 + kg * 4] = bv[p];
        }
        __syncthreads();
#pragma unroll
        for (int ks = 0; ks < 4; ks++) {
            const int k0 = ks * 8;
            unsigned a[2][4], bf[8][2];
#pragma unroll
            for (int mi = 0; mi < 2; mi++) {
                int r0 = (wm + mi * 16 + g) * 36 + k0 + c;
                a[mi][0] = __float_as_uint(As[r0]);
                a[mi][1] = __float_as_uint(As[r0 + 8 * 36]);
                a[mi][2] = __float_as_uint(As[r0 + 4]);
                a[mi][3] = __float_as_uint(As[r0 + 8 * 36 + 4]);
            }
#pragma unroll
            for (int ni = 0; ni < 8; ni++) {
                int r0 = (wn + ni * 8 + g) * 36 + k0 + c;
                bf[ni][0] = __float_as_uint(Bs[r0]);
                bf[ni][1] = __float_as_uint(Bs[r0 + 4]);
            }
#pragma unroll
            for (int mi = 0; mi < 2; mi++)
#pragma unroll
                for (int ni = 0; ni < 8; ni++)
                    asm volatile(
                        "mma.sync.aligned.m16n8k8.row.col.f32.tf32.tf32.f32 "
                        "{%0,%1,%2,%3},{%4,%5,%6,%7},{%8,%9},{%0,%1,%2,%3};"
                        : "+f"(acc[mi][ni][0]), "+f"(acc[mi][ni][1]),
                          "+f"(acc[mi][ni][2]), "+f"(acc[mi][ni][3])
                        : "r"(a[mi][0]), "r"(a[mi][1]), "r"(a[mi][2]), "r"(a[mi][3]),
                          "r"(bf[ni][0]), "r"(bf[ni][1]));
        }
    }
#pragma unroll
    for (int mi = 0; mi < 2; mi++) {
        const int r = bm + wm + mi * 16 + g;
#pragma unroll
        for (int ni = 0; ni < 8; ni++) {
            const int col = bn + wn + ni * 8 + 2 * c;
            const float b0 = bias[col], b1 = bias[col + 1];
            *(float2*)&C[(size_t)r * N + col]       = make_float2(acc[mi][ni][0] + b0, acc[mi][ni][1] + b1);
            *(float2*)&C[(size_t)(r + 8) * N + col] = make_float2(acc[mi][ni][2] + b0, acc[mi][ni][3] + b1);
        }
    }
}

// -------------------- persistent megakernel --------------------
__device__ __forceinline__ void grid_bar(unsigned target)
{
    __syncthreads();
    if (threadIdx.x == 0) {
        __threadfence();
        atomicAdd(&g_cnt, 1u);
        while (*((volatile unsigned*)&g_cnt) < target) { }
        __threadfence();
    }
    __syncthreads();
}

// 8 gate rows (2 units x 4 gates, row = g*512 + u0 + uu), one k-slice of LEN
template<int LEN, bool CG>
__device__ __forceinline__ void gate_slice(
    const float* __restrict__ x,     // per-lane (batch) base, LEN floats
    const float* __restrict__ w,     // W + u0*rowlen + wcol
    size_t rowlen, float acc[8])
{
#pragma unroll 2
    for (int k = 0; k < LEN; k += 4) {
        float4 xv = CG ? __ldcg((const float4*)(x + k)) : __ldg((const float4*)(x + k));
#pragma unroll
        for (int uu = 0; uu < 2; uu++)
#pragma unroll
            for (int gg = 0; gg < 4; gg++) {
                float4 wv = __ldg((const float4*)(w + ((size_t)(gg * 512 + uu)) * rowlen + k));
                acc[uu * 4 + gg] += wv.x * xv.x + wv.y * xv.y + wv.z * xv.z + wv.w * xv.w;
            }
    }
}

__global__ void __launch_bounds__(256, 1) megakernel(
    const float* __restrict__ enc, const float* __restrict__ vvec,
    const float* __restrict__ Wq, const float* __restrict__ bq,
    const float* __restrict__ Wih0, const float* __restrict__ Whh0,
    const float* __restrict__ bih0, const float* __restrict__ bhh0,
    const float* __restrict__ Wih1, const float* __restrict__ Whh1,
    const float* __restrict__ bih1, const float* __restrict__ bhh1)
{
    const int blk = blockIdx.x, tid = threadIdx.x;
    const int wid = tid >> 5, lane = tid & 31;
    const int gw = blk * 8 + wid;
    const int j0 = blk * 4;            // 4 units per block
    const int rg = wid >> 2;           // row group (2 units)
    const int kw = wid & 3;            // k-split id
    const int u0 = j0 + 2 * rg;

    __shared__ float s_buf[8 * 8 * 32];    // reductions (8KB)
    __shared__ float s_w[SS];
    __shared__ float s_c[2][128];
    __shared__ float s_red[16];

    unsigned bar = 0;

    for (int t = 0; t < TT; t++) {
        const int rbuf = t & 1, wbuf = rbuf ^ 1;

        // ---- P1: q projection: rows j0..j0+3, K=512 split 8 ways ----
        {
            const float* xq = g_h1[rbuf] + lane * HH + wid * 64;
            const float* wq = Wq + (size_t)j0 * HH + wid * 64;
            float qa[4] = {0.f, 0.f, 0.f, 0.f};
#pragma unroll 2
            for (int k = 0; k < 64; k += 4) {
                float4 xv = __ldcg((const float4*)(xq + k));
#pragma unroll
                for (int r = 0; r < 4; r++) {
                    float4 wv = __ldg((const float4*)(wq + (size_t)r * HH + k));
                    qa[r] += wv.x * xv.x + wv.y * xv.y + wv.z * xv.z + wv.w * xv.w;
                }
            }
#pragma unroll
            for (int r = 0; r < 4; r++) s_buf[(wid * 4 + r) * 32 + lane] = qa[r];
            __syncthreads();
            if (tid < 128) {
                int b = tid & 31, r = tid >> 5;
                float s = 0.f;
#pragma unroll
                for (int w2 = 0; w2 < 8; w2++) s += s_buf[(w2 * 4 + r) * 32 + b];
                g_qp[b * HH + j0 + r] = s + __ldg(bq + j0 + r);
            }
        }
        grid_bar(++bar * NB);

        // ---- P2: attention scores ----
        {
            const int b = gw >> 5, sbase = (gw & 31) * 8;
            float qv[16], vv[16];
#pragma unroll
            for (int i = 0; i < 16; i++) {
                qv[i] = __ldcg(&g_qp[b * HH + i * 32 + lane]);
                vv[i] = __ldg(vvec + i * 32 + lane);
            }
#pragma unroll
            for (int si = 0; si < 8; si++) {
                const float* kp = g_kp + ((size_t)b * SS + sbase + si) * HH;
                float acc = 0.f;
#pragma unroll
                for (int i = 0; i < 16; i++)
                    acc += vv[i] * tanh_fast(__ldg(kp + i * 32 + lane) + qv[i]);
#pragma unroll
                for (int o = 16; o; o >>= 1) acc += __shfl_xor_sync(0xffffffffu, acc, o);
                if (lane == 0) g_sc[b * SS + sbase + si] = acc;
            }
        }
        grid_bar(++bar * NB);

        // ---- P3: softmax + context (4 blocks per b, 128 e-cols each) ----
        {
            const int b = blk >> 2, ebase = (blk & 3) * 128;
            float x = __ldcg(&g_sc[b * SS + tid]);
            float m = x;
#pragma unroll
            for (int o = 16; o; o >>= 1) m = fmaxf(m, __shfl_xor_sync(0xffffffffu, m, o));
            if (lane == 0) s_red[wid] = m;
            __syncthreads();
            float bm = s_red[0];
#pragma unroll
            for (int w2 = 1; w2 < 8; w2++) bm = fmaxf(bm, s_red[w2]);
            float e = ex2f(1.44269504f * (x - bm));
            float se = e;
#pragma unroll
            for (int o = 16; o; o >>= 1) se += __shfl_xor_sync(0xffffffffu, se, o);
            if (lane == 0) s_red[8 + wid] = se;
            __syncthreads();
            float tot = 0.f;
#pragma unroll
            for (int w2 = 0; w2 < 8; w2++) tot += s_red[8 + w2];
            s_w[tid] = e * rcpf(tot);
            __syncthreads();

            const int el = tid & 127, sh = tid >> 7;
            const float* eb = enc + (size_t)b * SS * EENC + ebase + el;
            float acc = 0.f;
#pragma unroll 4
            for (int s = sh; s < SS; s += 2)
                acc += s_w[s] * __ldg(eb + (size_t)s * EENC);
            s_c[sh][el] = acc;
            __syncthreads();
            if (tid < 128) {
                float v = s_c[0][tid] + s_c[1][tid];
                g_ctx[b * EENC + ebase + tid] = v;
                g_A[((size_t)b * TT + t) * KLOG + HH + ebase + tid] = v;
            }
        }
        grid_bar(++bar * NB);

        // ---- P4: LSTM layer 0 (K = 256 emb + 512 ctx + 512 h) ----
        {
            float acc[8] = {0.f,0.f,0.f,0.f,0.f,0.f,0.f,0.f};
            const float* xe = g_emb2 + ((size_t)t * BB + lane) * EEMB + kw * 64;
            const float* xc = g_ctx + lane * EENC + kw * 128;
            const float* xh = g_h0[rbuf] + lane * HH + kw * 128;
            gate_slice<64,  false>(xe, Wih0 + (size_t)u0 * 768 + kw * 64,        768, acc);
            gate_slice<128, true >(xc, Wih0 + (size_t)u0 * 768 + 256 + kw * 128, 768, acc);
            gate_slice<128, true >(xh, Whh0 + (size_t)u0 * HH  + kw * 128,       HH,  acc);
#pragma unroll
            for (int a = 0; a < 8; a++) s_buf[(wid * 8 + a) * 32 + lane] = acc[a];
            __syncthreads();
            if (tid < 128) {
                int b = tid & 31, uu2 = tid >> 5;
                int j = j0 + uu2;
                int rg2 = uu2 >> 1, uul = uu2 & 1;
                float v[4];
#pragma unroll
                for (int gg = 0; gg < 4; gg++) {
                    float s = 0.f;
#pragma unroll
                    for (int kw2 = 0; kw2 < 4; kw2++)
                        s += s_buf[((rg2 * 4 + kw2) * 8 + uul * 4 + gg) * 32 + b];
                    v[gg] = s + __ldg(bih0 + gg * HH + j) + __ldg(bhh0 + gg * HH + j);
                }
                float iv = sigm(v[0]), fv = sigm(v[1]);
                float gv = tanh_acc(v[2]), ov = sigm(v[3]);
                float cn = fv * g_c0[j * 32 + b] + iv * gv;
                float hn = ov * tanh_acc(cn);
                g_c0[j * 32 + b] = cn;
                g_h0[wbuf][b * HH + j] = hn;
            }
        }
        grid_bar(++bar * NB);

        // ---- P5: LSTM layer 1 (K = 512 h0new + 512 h1prev) ----
        {
            float acc[8] = {0.f,0.f,0.f,0.f,0.f,0.f,0.f,0.f};
            const float* xa = g_h0[wbuf] + lane * HH + kw * 128;
            const float* xb = g_h1[rbuf] + lane * HH + kw * 128;
            gate_slice<128, true>(xa, Wih1 + (size_t)u0 * HH + kw * 128, HH, acc);
            gate_slice<128, true>(xb, Whh1 + (size_t)u0 * HH + kw * 128, HH, acc);
#pragma unroll
            for (int a = 0; a < 8; a++) s_buf[(wid * 8 + a) * 32 + lane] = acc[a];
            __syncthreads();
            if (tid < 128) {
                int b = tid & 31, uu2 = tid >> 5;
                int j = j0 + uu2;
                int rg2 = uu2 >> 1, uul = uu2 & 1;
                float v[4];
#pragma unroll
                for (int gg = 0; gg < 4; gg++) {
                    float s = 0.f;
#pragma unroll
                    for (int kw2 = 0; kw2 < 4; kw2++)
                        s += s_buf[((rg2 * 4 + kw2) * 8 + uul * 4 + gg) * 32 + b];
                    v[gg] = s + __ldg(bih1 + gg * HH + j) + __ldg(bhh1 + gg * HH + j);
                }
                float iv = sigm(v[0]), fv = sigm(v[1]);
                float gv = tanh_acc(v[2]), ov = sigm(v[3]);
                float cn = fv * g_c1[j * 32 + b] + iv * gv;
                float hn = ov * tanh_acc(cn);
                g_c1[j * 32 + b] = cn;
                g_h1[wbuf][b * HH + j] = hn;
                g_A[((size_t)b * TT + t) * KLOG + j] = hn;
            }
        }
        grid_bar(++bar * NB);
    }
}

__global__ void epilogue_kernel(float* __restrict__ out)
{
    int idx = blockIdx.x * blockDim.x + threadIdx.x;
    if (idx >= 2 * 2 * BB * HH) return;
    int part = idx >> 15;
    int rem = idx & 32767;
    int l = rem >> 14;
    int bb = (rem >> 9) & 31;
    int k = rem & 511;
    float v;
    if (part == 0) v = l ? g_h1[0][bb * HH + k] : g_h0[0][bb * HH + k];
    else           v = l ? g_c1[k * 32 + bb]    : g_c0[k * 32 + bb];
    out[(size_t)BB * TT * VV + idx] = v;
}

extern "C" void kernel_launch(void* const* d_in, const int* in_sizes, int n_in,
                              void* d_out, int out_size)
{
    const float* enc  = (const float*)d_in[0];
    const int*   tok  = (const int*)  d_in[1];
    const float* emb  = (const float*)d_in[2];
    const float* Wq   = (const float*)d_in[3];
    const float* bq   = (const float*)d_in[4];
    const float* Wk   = (const float*)d_in[5];
    const float* bk   = (const float*)d_in[6];
    const float* vvec = (const float*)d_in[7];
    const float* Wih0 = (const float*)d_in[8];
    const float* Whh0 = (const float*)d_in[9];
    const float* bih0 = (const float*)d_in[10];
    const float* bhh0 = (const float*)d_in[11];
    const float* Wih1 = (const float*)d_in[12];
    const float* Whh1 = (const float*)d_in[13];
    const float* bih1 = (const float*)d_in[14];
    const float* bhh1 = (const float*)d_in[15];
    const float* Wout = (const float*)d_in[16];
    const float* bout = (const float*)d_in[17];
    float* out = (float*)d_out;

    float* kp;    cudaGetSymbolAddress((void**)&kp,  g_kp);
    float* Amat;  cudaGetSymbolAddress((void**)&Amat, g_A);

    init_kernel<<<(BB * HH + 255) / 256, 256>>>();
    embed_kernel<<<(TT * BB * EEMB + 255) / 256, 256>>>(tok, emb);

    // key_proj = enc @ Wk^T + bk : M=8192, N=512, K=512
    {
        dim3 grid(HH / 128, (BB * SS) / 128);
        gemm_tf32<<<grid, 256>>>(enc, Wk, bk, kp, BB * SS, HH, EENC);
    }

    megakernel<<<NB, 256>>>(enc, vvec, Wq, bq,
                            Wih0, Whh0, bih0, bhh0,
                            Wih1, Whh1, bih1, bhh1);

    // logits: M=4096, N=32000, K=1024
    {
        dim3 grid(VV / 128, (BB * TT) / 128);
        gemm_tf32<<<grid, 256>>>(Amat, Wout, bout, out, BB * TT, VV, KLOG);
    }

    epilogue_kernel<<<(2 * 2 * BB * HH + 255) / 256, 256>>>(out);
}

// round 6
// speedup vs baseline: 3.3803x; 1.2599x over previous
#include <cuda_runtime.h>
#include <cstdint>

#define BB 32
#define SS 256
#define TT 128
#define HH 512
#define EENC 512
#define EEMB 256
#define VV 32000
#define KLOG 1024
#define NB 128
#define NTHR 512

typedef unsigned long long u64;

__device__ float g_kp[BB * SS * HH];        // [b*S+s][h]
__device__ float g_embT[TT * EEMB * BB];    // [t][k][b]
__device__ float g_h0T[2][HH * BB];         // [j][b] ping-pong
__device__ float g_h1T[2][HH * BB];
__device__ float g_c0[HH * BB];             // [j][b]
__device__ float g_c1[HH * BB];
__device__ float g_qp[BB * HH];             // [b][h]
__device__ float g_ctxT[EENC * BB];         // [e][b]
__device__ float g_sc[BB * SS];
__device__ float g_A[BB * TT * KLOG];
__device__ unsigned g_cnt;

__device__ __forceinline__ float ex2f(float x){ float y; asm("ex2.approx.f32 %0,%1;":"=f"(y):"f"(x)); return y; }
__device__ __forceinline__ float rcpf(float x){ float y; asm("rcp.approx.f32 %0,%1;":"=f"(y):"f"(x)); return y; }
__device__ __forceinline__ float tanh_fast(float x){ float y; asm("tanh.approx.f32 %0,%1;":"=f"(y):"f"(x)); return y; }
__device__ __forceinline__ float sigm(float x){ return rcpf(1.f + ex2f(-1.44269504f * x)); }
__device__ __forceinline__ float tanh_acc(float x){ float e = ex2f(2.88539008f * x); return 1.f - 2.f * rcpf(e + 1.f); }

__device__ __forceinline__ u64 pack2(float lo, float hi){ u64 r; asm("mov.b64 %0,{%1,%2};":"=l"(r):"f"(lo),"f"(hi)); return r; }
__device__ __forceinline__ void fma2(u64& d, u64 a, u64 b){ asm("fma.rn.f32x2 %0,%1,%2,%0;":"+l"(d):"l"(a),"l"(b)); }
__device__ __forceinline__ float sum2(u64 v){ float lo, hi; asm("mov.b64 {%0,%1},%2;":"=f"(lo),"=f"(hi):"l"(v)); return lo + hi; }

__global__ void init_kernel()
{
    int i = blockIdx.x * blockDim.x + threadIdx.x;
    if (i < HH * BB) {
        g_h0T[0][i] = 0.f; g_h1T[0][i] = 0.f;
        g_c0[i] = 0.f;     g_c1[i] = 0.f;
    }
    if (i == 0) g_cnt = 0u;
}

__global__ void embed_kernel(const int* __restrict__ tok, const float* __restrict__ emb)
{
    int idx = blockIdx.x * blockDim.x + threadIdx.x;
    if (idx >= TT * EEMB * BB) return;
    int b = idx & 31, k = (idx >> 5) & (EEMB - 1), t = idx >> 13;
    g_embT[idx] = emb[(size_t)tok[b * TT + t] * EEMB + k];
}

// C[M,N] = A[M,K] @ Bw[N,K]^T + bias[N], tf32 mma
__global__ void __launch_bounds__(256) gemm_tf32(
    const float* __restrict__ A, const float* __restrict__ Bw,
    const float* __restrict__ bias, float* __restrict__ C,
    int M, int N, int K)
{
    __shared__ float As[128 * 36];
    __shared__ float Bs[128 * 36];
    const int tid = threadIdx.x, lane = tid & 31, warp = tid >> 5;
    const int g = lane >> 2, c = lane & 3;
    const int wm = (warp >> 1) * 32, wn = (warp & 1) * 64;
    const int bm = blockIdx.y * 128, bn = blockIdx.x * 128;
    const int kg = tid & 7, rb = tid >> 3;
    const float* Aptr = A + (size_t)(bm + rb) * K + kg * 4;
    const float* Bptr = Bw + (size_t)(bn + rb) * K + kg * 4;

    float acc[2][8][4];
#pragma unroll
    for (int mi = 0; mi < 2; mi++)
#pragma unroll
        for (int ni = 0; ni < 8; ni++) { acc[mi][ni][0]=0;acc[mi][ni][1]=0;acc[mi][ni][2]=0;acc[mi][ni][3]=0; }

    for (int kt = 0; kt < K; kt += 32) {
        float4 av[4], bv[4];
#pragma unroll
        for (int p = 0; p < 4; p++) {
            av[p] = *(const float4*)(Aptr + (size_t)(p * 32) * K + kt);
            bv[p] = *(const float4*)(Bptr + (size_t)(p * 32) * K + kt);
        }
        __syncthreads();
#pragma unroll
        for (int p = 0; p < 4; p++) {
            *(float4*)&As[(rb + p * 32) * 36 + kg * 4] = av[p];
            *(float4*)&Bs[(rb + p * 32) * 36 + kg * 4] = bv[p];
        }
        __syncthreads();
#pragma unroll
        for (int ks = 0; ks < 4; ks++) {
            const int k0 = ks * 8;
            unsigned a[2][4], bf[8][2];
#pragma unroll
            for (int mi = 0; mi < 2; mi++) {
                int r0 = (wm + mi * 16 + g) * 36 + k0 + c;
                a[mi][0] = __float_as_uint(As[r0]);
                a[mi][1] = __float_as_uint(As[r0 + 8 * 36]);
                a[mi][2] = __float_as_uint(As[r0 + 4]);
                a[mi][3] = __float_as_uint(As[r0 + 8 * 36 + 4]);
            }
#pragma unroll
            for (int ni = 0; ni < 8; ni++) {
                int r0 = (wn + ni * 8 + g) * 36 + k0 + c;
                bf[ni][0] = __float_as_uint(Bs[r0]);
                bf[ni][1] = __float_as_uint(Bs[r0 + 4]);
            }
#pragma unroll
            for (int mi = 0; mi < 2; mi++)
#pragma unroll
                for (int ni = 0; ni < 8; ni++)
                    asm volatile(
                        "mma.sync.aligned.m16n8k8.row.col.f32.tf32.tf32.f32 "
                        "{%0,%1,%2,%3},{%4,%5,%6,%7},{%8,%9},{%0,%1,%2,%3};"
                        : "+f"(acc[mi][ni][0]), "+f"(acc[mi][ni][1]),
                          "+f"(acc[mi][ni][2]), "+f"(acc[mi][ni][3])
                        : "r"(a[mi][0]), "r"(a[mi][1]), "r"(a[mi][2]), "r"(a[mi][3]),
                          "r"(bf[ni][0]), "r"(bf[ni][1]));
        }
    }
#pragma unroll
    for (int mi = 0; mi < 2; mi++) {
        const int r = bm + wm + mi * 16 + g;
#pragma unroll
        for (int ni = 0; ni < 8; ni++) {
            const int col = bn + wn + ni * 8 + 2 * c;
            const float b0 = bias[col], b1 = bias[col + 1];
            *(float2*)&C[(size_t)r * N + col]       = make_float2(acc[mi][ni][0] + b0, acc[mi][ni][1] + b1);
            *(float2*)&C[(size_t)(r + 8) * N + col] = make_float2(acc[mi][ni][2] + b0, acc[mi][ni][3] + b1);
        }
    }
}

// -------------------- persistent megakernel --------------------
__device__ __forceinline__ void grid_bar(unsigned target)
{
    __syncthreads();
    if (threadIdx.x == 0) {
        __threadfence();
        atomicAdd(&g_cnt, 1u);
        while (*((volatile unsigned*)&g_cnt) < target) { }
        __threadfence();
    }
    __syncthreads();
}

// 8 gate rows (2 units x 4 gates), x in [k][batch] layout (lane = batch).
template<int KLEN, bool CG>
__device__ __forceinline__ void gate8(
    const float* __restrict__ x, const float* __restrict__ w,
    int rowlen, u64 acc[8], int lane)
{
#pragma unroll 4
    for (int k = 0; k < KLEN; k += 4) {
        float x0 = CG ? __ldcg(x + (k + 0) * 32 + lane) : __ldg(x + (k + 0) * 32 + lane);
        float x1 = CG ? __ldcg(x + (k + 1) * 32 + lane) : __ldg(x + (k + 1) * 32 + lane);
        float x2 = CG ? __ldcg(x + (k + 2) * 32 + lane) : __ldg(x + (k + 2) * 32 + lane);
        float x3 = CG ? __ldcg(x + (k + 3) * 32 + lane) : __ldg(x + (k + 3) * 32 + lane);
        u64 xp0 = pack2(x0, x1), xp1 = pack2(x2, x3);
#pragma unroll
        for (int uu = 0; uu < 2; uu++)
#pragma unroll
            for (int gg = 0; gg < 4; gg++) {
                float4 wv = __ldg((const float4*)(w + (size_t)(gg * 512 + uu) * rowlen + k));
                fma2(acc[uu * 4 + gg], pack2(wv.x, wv.y), xp0);
                fma2(acc[uu * 4 + gg], pack2(wv.z, wv.w), xp1);
            }
    }
}

__global__ void __launch_bounds__(NTHR, 1) megakernel(
    const float* __restrict__ enc, const float* __restrict__ vvec,
    const float* __restrict__ Wq, const float* __restrict__ bq,
    const float* __restrict__ Wih0, const float* __restrict__ Whh0,
    const float* __restrict__ bih0, const float* __restrict__ bhh0,
    const float* __restrict__ Wih1, const float* __restrict__ Whh1,
    const float* __restrict__ bih1, const float* __restrict__ bhh1)
{
    const int blk = blockIdx.x, tid = threadIdx.x;
    const int wid = tid >> 5, lane = tid & 31;
    const int j0 = blk * 4;            // 4 units per block
    const int rg = wid >> 3;           // row group (2 units each)
    const int kw8 = wid & 7;           // 8-way k split for lstm
    const int u0 = j0 + 2 * rg;

    __shared__ float s_buf[128 * 33];  // 16.9KB reduction buffer
    __shared__ float s_w[SS];
    __shared__ float s_c[4][128];
    __shared__ float s_red[32];

    unsigned bar = 0;

    for (int t = 0; t < TT; t++) {
        const int rbuf = t & 1, wbuf = rbuf ^ 1;

        // ---- P1: q projection: rows j0..j0+3, K=512 split 16 ways ----
        {
            const float* xq = g_h1T[rbuf] + (wid * 32) * 32;
            const float* wq = Wq + (size_t)j0 * HH + wid * 32;
            u64 qa[4] = {0, 0, 0, 0};
#pragma unroll 4
            for (int k = 0; k < 32; k += 4) {
                float x0 = __ldcg(xq + (k + 0) * 32 + lane);
                float x1 = __ldcg(xq + (k + 1) * 32 + lane);
                float x2 = __ldcg(xq + (k + 2) * 32 + lane);
                float x3 = __ldcg(xq + (k + 3) * 32 + lane);
                u64 xp0 = pack2(x0, x1), xp1 = pack2(x2, x3);
#pragma unroll
                for (int r = 0; r < 4; r++) {
                    float4 wv = __ldg((const float4*)(wq + (size_t)r * HH + k));
                    fma2(qa[r], pack2(wv.x, wv.y), xp0);
                    fma2(qa[r], pack2(wv.z, wv.w), xp1);
                }
            }
#pragma unroll
            for (int r = 0; r < 4; r++) s_buf[(wid * 4 + r) * 33 + lane] = sum2(qa[r]);
            __syncthreads();
            if (tid < 128) {
                int b = tid & 31, r = tid >> 5;
                float s = 0.f;
#pragma unroll
                for (int w2 = 0; w2 < 16; w2++) s += s_buf[(w2 * 4 + r) * 33 + b];
                g_qp[b * HH + j0 + r] = s + __ldg(bq + j0 + r);
            }
        }
        grid_bar(++bar * NB);

        // ---- P2: attention scores (2048 warps, 4 s each) ----
        {
            const int gw = blk * 16 + wid;
            const int b = gw >> 6, sq = (gw & 63) * 4;
            float qv[16], vv[16];
#pragma unroll
            for (int i = 0; i < 16; i++) {
                qv[i] = __ldcg(&g_qp[b * HH + i * 32 + lane]);
                vv[i] = __ldg(vvec + i * 32 + lane);
            }
#pragma unroll
            for (int si = 0; si < 4; si++) {
                const float* kp = g_kp + ((size_t)b * SS + sq + si) * HH;
                float acc = 0.f;
#pragma unroll
                for (int i = 0; i < 16; i++)
                    acc += vv[i] * tanh_fast(__ldg(kp + i * 32 + lane) + qv[i]);
#pragma unroll
                for (int o = 16; o; o >>= 1) acc += __shfl_xor_sync(0xffffffffu, acc, o);
                if (lane == 0) g_sc[b * SS + sq + si] = acc;
            }
        }
        grid_bar(++bar * NB);

        // ---- P3: softmax + context (4 blocks per b, 128 e-cols each) ----
        {
            const int b = blk >> 2, ebase = (blk & 3) * 128;
            float x = (tid < 256) ? __ldcg(&g_sc[b * SS + tid]) : -1e30f;
            float m = x;
#pragma unroll
            for (int o = 16; o; o >>= 1) m = fmaxf(m, __shfl_xor_sync(0xffffffffu, m, o));
            if (lane == 0) s_red[wid] = m;
            __syncthreads();
            float bm = s_red[0];
#pragma unroll
            for (int w2 = 1; w2 < 16; w2++) bm = fmaxf(bm, s_red[w2]);
            float e = ex2f(1.44269504f * (x - bm));   // 0 for tid>=256
            float se = e;
#pragma unroll
            for (int o = 16; o; o >>= 1) se += __shfl_xor_sync(0xffffffffu, se, o);
            if (lane == 0) s_red[16 + wid] = se;
            __syncthreads();
            float tot = 0.f;
#pragma unroll
            for (int w2 = 0; w2 < 16; w2++) tot += s_red[16 + w2];
            if (tid < 256) s_w[tid] = e * rcpf(tot);
            __syncthreads();

            const int el = tid & 127, sh = tid >> 7;   // 4-way s split
            const float* eb = enc + (size_t)b * SS * EENC + ebase + el;
            float acc = 0.f;
#pragma unroll 4
            for (int s = sh; s < SS; s += 4)
                acc += s_w[s] * __ldg(eb + (size_t)s * EENC);
            s_c[sh][el] = acc;
            __syncthreads();
            if (tid < 128) {
                float v = s_c[0][tid] + s_c[1][tid] + s_c[2][tid] + s_c[3][tid];
                g_ctxT[(ebase + tid) * 32 + b] = v;
                g_A[((size_t)b * TT + t) * KLOG + HH + ebase + tid] = v;
            }
        }
        grid_bar(++bar * NB);

        // ---- P4: LSTM layer 0 (K = 256 emb + 512 ctx + 512 h) ----
        {
            u64 acc[8] = {0, 0, 0, 0, 0, 0, 0, 0};
            gate8<32, false>(g_embT + (size_t)t * EEMB * 32 + (kw8 * 32) * 32,
                             Wih0 + (size_t)u0 * 768 + kw8 * 32, 768, acc, lane);
            gate8<64, true >(g_ctxT + (kw8 * 64) * 32,
                             Wih0 + (size_t)u0 * 768 + 256 + kw8 * 64, 768, acc, lane);
            gate8<64, true >(g_h0T[rbuf] + (kw8 * 64) * 32,
                             Whh0 + (size_t)u0 * HH + kw8 * 64, HH, acc, lane);
#pragma unroll
            for (int a = 0; a < 8; a++) s_buf[(wid * 8 + a) * 33 + lane] = sum2(acc[a]);
            __syncthreads();
            if (tid < 128) {
                int b = tid & 31, uu2 = tid >> 5;
                int j = j0 + uu2;
                int rg2 = uu2 >> 1, uul = uu2 & 1;
                float v[4];
#pragma unroll
                for (int gg = 0; gg < 4; gg++) {
                    float s = 0.f;
#pragma unroll
                    for (int kk = 0; kk < 8; kk++)
                        s += s_buf[(((rg2 * 8 + kk) * 8) + uul * 4 + gg) * 33 + b];
                    v[gg] = s + __ldg(bih0 + gg * HH + j) + __ldg(bhh0 + gg * HH + j);
                }
                float iv = sigm(v[0]), fv = sigm(v[1]);
                float gv = tanh_acc(v[2]), ov = sigm(v[3]);
                float cn = fv * g_c0[j * 32 + b] + iv * gv;
                float hn = ov * tanh_acc(cn);
                g_c0[j * 32 + b] = cn;
                g_h0T[wbuf][j * 32 + b] = hn;
            }
        }
        grid_bar(++bar * NB);

        // ---- P5: LSTM layer 1 (K = 512 h0new + 512 h1prev) ----
        {
            u64 acc[8] = {0, 0, 0, 0, 0, 0, 0, 0};
            gate8<64, true>(g_h0T[wbuf] + (kw8 * 64) * 32,
                            Wih1 + (size_t)u0 * HH + kw8 * 64, HH, acc, lane);
            gate8<64, true>(g_h1T[rbuf] + (kw8 * 64) * 32,
                            Whh1 + (size_t)u0 * HH + kw8 * 64, HH, acc, lane);
#pragma unroll
            for (int a = 0; a < 8; a++) s_buf[(wid * 8 + a) * 33 + lane] = sum2(acc[a]);
            __syncthreads();
            if (tid < 128) {
                int b = tid & 31, uu2 = tid >> 5;
                int j = j0 + uu2;
                int rg2 = uu2 >> 1, uul = uu2 & 1;
                float v[4];
#pragma unroll
                for (int gg = 0; gg < 4; gg++) {
                    float s = 0.f;
#pragma unroll
                    for (int kk = 0; kk < 8; kk++)
                        s += s_buf[(((rg2 * 8 + kk) * 8) + uul * 4 + gg) * 33 + b];
                    v[gg] = s + __ldg(bih1 + gg * HH + j) + __ldg(bhh1 + gg * HH + j);
                }
                float iv = sigm(v[0]), fv = sigm(v[1]);
                float gv = tanh_acc(v[2]), ov = sigm(v[3]);
                float cn = fv * g_c1[j * 32 + b] + iv * gv;
                float hn = ov * tanh_acc(cn);
                g_c1[j * 32 + b] = cn;
                g_h1T[wbuf][j * 32 + b] = hn;
                g_A[((size_t)b * TT + t) * KLOG + j] = hn;
            }
        }
        grid_bar(++bar * NB);
    }
}

__global__ void epilogue_kernel(float* __restrict__ out)
{
    int idx = blockIdx.x * blockDim.x + threadIdx.x;
    if (idx >= 2 * 2 * BB * HH) return;
    int part = idx >> 15;
    int rem = idx & 32767;
    int l = rem >> 14;
    int bb = (rem >> 9) & 31;
    int k = rem & 511;
    float v;
    if (part == 0) v = l ? g_h1T[0][k * 32 + bb] : g_h0T[0][k * 32 + bb];
    else           v = l ? g_c1[k * 32 + bb]     : g_c0[k * 32 + bb];
    out[(size_t)BB * TT * VV + idx] = v;
}

extern "C" void kernel_launch(void* const* d_in, const int* in_sizes, int n_in,
                              void* d_out, int out_size)
{
    const float* enc  = (const float*)d_in[0];
    const int*   tok  = (const int*)  d_in[1];
    const float* emb  = (const float*)d_in[2];
    const float* Wq   = (const float*)d_in[3];
    const float* bq   = (const float*)d_in[4];
    const float* Wk   = (const float*)d_in[5];
    const float* bk   = (const float*)d_in[6];
    const float* vvec = (const float*)d_in[7];
    const float* Wih0 = (const float*)d_in[8];
    const float* Whh0 = (const float*)d_in[9];
    const float* bih0 = (const float*)d_in[10];
    const float* bhh0 = (const float*)d_in[11];
    const float* Wih1 = (const float*)d_in[12];
    const float* Whh1 = (const float*)d_in[13];
    const float* bih1 = (const float*)d_in[14];
    const float* bhh1 = (const float*)d_in[15];
    const float* Wout = (const float*)d_in[16];
    const float* bout = (const float*)d_in[17];
    float* out = (float*)d_out;

    float* kp;    cudaGetSymbolAddress((void**)&kp,  g_kp);
    float* Amat;  cudaGetSymbolAddress((void**)&Amat, g_A);

    init_kernel<<<(HH * BB + 255) / 256, 256>>>();
    embed_kernel<<<(TT * EEMB * BB + 255) / 256, 256>>>(tok, emb);

    // key_proj = enc @ Wk^T + bk : M=8192, N=512, K=512
    {
        dim3 grid(HH / 128, (BB * SS) / 128);
        gemm_tf32<<<grid, 256>>>(enc, Wk, bk, kp, BB * SS, HH, EENC);
    }

    megakernel<<<NB, NTHR>>>(enc, vvec, Wq, bq,
                             Wih0, Whh0, bih0, bhh0,
                             Wih1, Whh1, bih1, bhh1);

    // logits: M=4096, N=32000, K=1024
    {
        dim3 grid(VV / 128, (BB * TT) / 128);
        gemm_tf32<<<grid, 256>>>(Amat, Wout, bout, out, BB * TT, VV, KLOG);
    }

    epilogue_kernel<<<(2 * 2 * BB * HH + 255) / 256, 256>>>(out);
}